// round 17
// baseline (speedup 1.0000x reference)
#include <cuda_runtime.h>
#include <cstdint>
#include <math.h>

#define H      128
#define HH     (H * H)
#define KNB    48
#define NN     2048
#define BNTOT  4096
#define XP     132          // activation tile pitch (floats)
#define WPQ    36           // weight quarter pitch (floats, cp.async path)

// weight matrix slots in g_Wt (all 128x128 [n][k] natural order, tf32-rounded)
#define W_E1   0
#define W_2T   1
#define W_3T   2
#define W_11E  3
#define W_12T  4
#define W_13T  5
#define W_1V   6
#define W_1G   7
#define W_1A   8
#define W_11V  9
#define W_11G  10
#define W_INT  11   // 11..14: W_in^T chunks
#define W_OUTT 15   // 15..18: W_out^T chunks

__device__ float g_Wt[19 * HH];
__device__ float g_D1[BNTOT * H];
__device__ float g_P1[BNTOT * H];
__device__ float g_D2[BNTOT * H];
__device__ float g_P2[BNTOT * H];
__device__ float g_hV1[BNTOT * H];

__device__ __forceinline__ float to_tf32(float x) {
    uint32_t u;
    asm("cvt.rna.tf32.f32 %0, %1;" : "=r"(u) : "f"(x));
    return __uint_as_float(u);
}

__device__ __forceinline__ float gelu_exact(float x) {
    return 0.5f * x * (1.0f + erff(x * 0.70710678118654752f));
}

__device__ __forceinline__ void mma_tf32(float d[4], const uint32_t a[4], const uint32_t b[2]) {
    asm volatile("mma.sync.aligned.m16n8k8.row.col.f32.tf32.tf32.f32 "
                 "{%0,%1,%2,%3}, {%4,%5,%6,%7}, {%8,%9}, {%0,%1,%2,%3};"
                 : "+f"(d[0]), "+f"(d[1]), "+f"(d[2]), "+f"(d[3])
                 : "r"(a[0]), "r"(a[1]), "r"(a[2]), "r"(a[3]), "r"(b[0]), "r"(b[1]));
}

// ---------------- async stage of one 32-k quarter (128n x 32k) into buf ----------------
__device__ __forceinline__ void stage_q_async(float* __restrict__ buf,
                                              const float* __restrict__ Wg, int q, int tid) {
    uint32_t base = (uint32_t)__cvta_generic_to_shared(buf);
#pragma unroll
    for (int i = 0; i < 4; i++) {
        int idx = tid + 256 * i;
        int n = idx >> 3, qd = idx & 7;
        asm volatile("cp.async.cg.shared.global [%0], [%1], 16;"
                     :: "r"(base + (uint32_t)((n * WPQ + qd * 4) * 4)),
                        "l"(Wg + n * H + q * 32 + qd * 4));
    }
    asm volatile("cp.async.commit_group;");
}

// ---------------- async stage of a 128x128 activation tile (raw fp32) ----------------
__device__ __forceinline__ void stage_rows_async(float* __restrict__ sX,
                                                 const float* __restrict__ src, int tid) {
    uint32_t base = (uint32_t)__cvta_generic_to_shared(sX);
    const int r = tid >> 1, ch = (tid & 1) * 64;
    uint32_t dst = base + (uint32_t)((r * XP + ch) * 4);
    const float* s = src + (size_t)r * H + ch;
#pragma unroll
    for (int c = 0; c < 64; c += 4)
        asm volatile("cp.async.cg.shared.global [%0], [%1], 16;"
                     :: "r"(dst + (uint32_t)(c * 4)), "l"(s + c));
    asm volatile("cp.async.commit_group;");
}

// ---------------- 128x128x128 tf32 GEMM, db async + cross-GEMM prefetch ----------------
// Slot convention: A float2 at 2lc -> slots (a0,a2)=(X[2lc],X[2lc+1]); B float2 natural.
__device__ __forceinline__ void gemm256_db(const float* __restrict__ sX,
                                           float* __restrict__ sW0, float* __restrict__ sW1,
                                           const float* __restrict__ Wg,
                                           const float* __restrict__ Wnext, bool primed,
                                           int tid, float acc[2][8][4]) {
    const int w = tid >> 5, lane = tid & 31;
    const int wm = w & 3, wn = w >> 2;
    const int lr = lane >> 2, lc = lane & 3;
    const float* sXw = sX + (wm * 32 + lr) * XP + 2 * lc;

    if (!primed) stage_q_async(sW0, Wg, 0, tid);
#pragma unroll
    for (int q = 0; q < 4; q++) {
        asm volatile("cp.async.wait_group 0;");
        __syncthreads();
        if (q < 3) stage_q_async((q & 1) ? sW0 : sW1, Wg, q + 1, tid);
        else if (Wnext) stage_q_async(sW0, Wnext, 0, tid);
        const float* bq = (q & 1) ? sW1 : sW0;
        const float* sWb = bq + (wn * 64 + lr) * WPQ + 2 * lc;
#pragma unroll
        for (int k8 = 0; k8 < 4; k8++) {
            const int kl = k8 * 8;
            uint32_t a[2][4];
#pragma unroll
            for (int mt = 0; mt < 2; mt++) {
                const float* ap = sXw + mt * (16 * XP) + q * 32 + kl;
                float2 lo = *(const float2*)(ap);
                float2 hi = *(const float2*)(ap + 8 * XP);
                a[mt][0] = __float_as_uint(lo.x);
                a[mt][2] = __float_as_uint(lo.y);
                a[mt][1] = __float_as_uint(hi.x);
                a[mt][3] = __float_as_uint(hi.y);
            }
#pragma unroll
            for (int nt = 0; nt < 8; nt++) {
                float2 bv = *(const float2*)(sWb + nt * (8 * WPQ) + kl);
                uint32_t b[2] = {__float_as_uint(bv.x), __float_as_uint(bv.y)};
                mma_tf32(acc[0][nt], a[0], b);
                mma_tf32(acc[1][nt], a[1], b);
            }
        }
    }
}

// ---------------- 64x128x128 tf32 GEMM, db async + prefetch (warp tile 16x64) ----------
__device__ __forceinline__ void gemm64_db(const float* __restrict__ sX,
                                          float* __restrict__ sW0, float* __restrict__ sW1,
                                          const float* __restrict__ Wg,
                                          const float* __restrict__ Wnext, bool primed,
                                          int tid, float acc[8][4]) {
    const int w = tid >> 5, lane = tid & 31;
    const int wm = w & 3, wn = w >> 2;
    const int lr = lane >> 2, lc = lane & 3;
    const float* sXw = sX + (wm * 16 + lr) * XP + 2 * lc;

    if (!primed) stage_q_async(sW0, Wg, 0, tid);
#pragma unroll
    for (int q = 0; q < 4; q++) {
        asm volatile("cp.async.wait_group 0;");
        __syncthreads();
        if (q < 3) stage_q_async((q & 1) ? sW0 : sW1, Wg, q + 1, tid);
        else if (Wnext) stage_q_async(sW0, Wnext, 0, tid);
        const float* bq = (q & 1) ? sW1 : sW0;
        const float* sWb = bq + (wn * 64 + lr) * WPQ + 2 * lc;
#pragma unroll
        for (int k8 = 0; k8 < 4; k8++) {
            const int kl = k8 * 8;
            const float* ap = sXw + q * 32 + kl;
            float2 lo = *(const float2*)(ap);
            float2 hi = *(const float2*)(ap + 8 * XP);
            uint32_t a[4];
            a[0] = __float_as_uint(lo.x);
            a[2] = __float_as_uint(lo.y);
            a[1] = __float_as_uint(hi.x);
            a[3] = __float_as_uint(hi.y);
#pragma unroll
            for (int nt = 0; nt < 8; nt++) {
                float2 bv = *(const float2*)(sWb + nt * (8 * WPQ) + kl);
                uint32_t b[2] = {__float_as_uint(bv.x), __float_as_uint(bv.y)};
                mma_tf32(acc[nt], a, b);
            }
        }
    }
}

// ---------------- 32x128x128 tf32 GEMM, db async + prefetch (8 warps across n) --------
__device__ __forceinline__ void gemm32_db(const float* __restrict__ sX,
                                          float* __restrict__ sW0, float* __restrict__ sW1,
                                          const float* __restrict__ Wg,
                                          const float* __restrict__ Wnext, bool primed,
                                          int tid, float acc[2][2][4]) {
    const int w = tid >> 5, lane = tid & 31;
    const int lr = lane >> 2, lc = lane & 3;
    const float* sXw = sX + lr * XP + 2 * lc;

    if (!primed) stage_q_async(sW0, Wg, 0, tid);
#pragma unroll
    for (int q = 0; q < 4; q++) {
        asm volatile("cp.async.wait_group 0;");
        __syncthreads();
        if (q < 3) stage_q_async((q & 1) ? sW0 : sW1, Wg, q + 1, tid);
        else if (Wnext) stage_q_async(sW0, Wnext, 0, tid);
        const float* bq = (q & 1) ? sW1 : sW0;
        const float* sWb = bq + (w * 16 + lr) * WPQ + 2 * lc;
#pragma unroll
        for (int k8 = 0; k8 < 4; k8++) {
            const int kl = k8 * 8;
            uint32_t a[2][4];
#pragma unroll
            for (int mt = 0; mt < 2; mt++) {
                const float* ap = sXw + mt * (16 * XP) + q * 32 + kl;
                float2 lo = *(const float2*)(ap);
                float2 hi = *(const float2*)(ap + 8 * XP);
                a[mt][0] = __float_as_uint(lo.x);
                a[mt][2] = __float_as_uint(lo.y);
                a[mt][1] = __float_as_uint(hi.x);
                a[mt][3] = __float_as_uint(hi.y);
            }
#pragma unroll
            for (int nt = 0; nt < 2; nt++) {
                float2 bv = *(const float2*)(sWb + nt * (8 * WPQ) + kl);
                uint32_t b[2] = {__float_as_uint(bv.x), __float_as_uint(bv.y)};
                mma_tf32(acc[0][nt], a[0], b);
                mma_tf32(acc[1][nt], a[1], b);
            }
        }
    }
}

__device__ __forceinline__ void zero_acc(float acc[2][8][4]) {
#pragma unroll
    for (int mt = 0; mt < 2; mt++)
#pragma unroll
        for (int nt = 0; nt < 8; nt++)
#pragma unroll
            for (int q = 0; q < 4; q++) acc[mt][nt][q] = 0.f;
}

__device__ __forceinline__ void zero_acc8(float acc[8][4]) {
#pragma unroll
    for (int nt = 0; nt < 8; nt++)
#pragma unroll
        for (int q = 0; q < 4; q++) acc[nt][q] = 0.f;
}

__device__ __forceinline__ void zero_acc32(float acc[2][2][4]) {
#pragma unroll
    for (int mt = 0; mt < 2; mt++)
#pragma unroll
        for (int nt = 0; nt < 2; nt++)
#pragma unroll
            for (int q = 0; q < 4; q++) acc[mt][nt][q] = 0.f;
}

__device__ __forceinline__ void store_acc(float* __restrict__ dst, int tid,
                                          const float acc[2][8][4]) {
    const int w = tid >> 5, lane = tid & 31;
    const int wm = w & 3, wn = w >> 2;
    const int lr = lane >> 2, lc = lane & 3;
    float* cx = dst + (wm * 32 + lr) * XP + wn * 64 + 2 * lc;
#pragma unroll
    for (int mt = 0; mt < 2; mt++)
#pragma unroll
        for (int nt = 0; nt < 8; nt++) {
            *(float2*)(cx + mt * (16 * XP) + nt * 8) =
                make_float2(acc[mt][nt][0], acc[mt][nt][1]);
            *(float2*)(cx + mt * (16 * XP) + 8 * XP + nt * 8) =
                make_float2(acc[mt][nt][2], acc[mt][nt][3]);
        }
}

// register epi1: sX = gelu(acc + sD[node(row)] + P[src(row)])  (fp32; MMA truncates)
__device__ __forceinline__ void epi1_reg(float* __restrict__ sX, int tid, int t128,
                                         const float acc[2][8][4],
                                         const float* __restrict__ Pbase,
                                         const int* __restrict__ sIdxT,
                                         const float* __restrict__ sD) {
    const int w = tid >> 5, lane = tid & 31;
    const int wm = w & 3, wn = w >> 2;
    const int lr = lane >> 2, lc = lane & 3;
#pragma unroll
    for (int mt = 0; mt < 2; mt++) {
#pragma unroll
        for (int hf = 0; hf < 2; hf++) {
            int r = wm * 32 + mt * 16 + lr + hf * 8;
            int src = sIdxT[r];
            int nl = (t128 + r) / KNB;
            const float* pr = Pbase + (size_t)src * H;
            const float* dn = sD + nl * H;
            float* xrow = sX + r * XP;
            const int ai = hf * 2;
#pragma unroll
            for (int nt = 0; nt < 8; nt++) {
                int col = wn * 64 + nt * 8 + 2 * lc;
                float2 p = *(const float2*)(pr + col);
                float2 d = *(const float2*)(dn + col);
                *(float2*)(xrow + col) =
                    make_float2(gelu_exact(acc[mt][nt][ai] + d.x + p.x),
                                gelu_exact(acc[mt][nt][ai + 1] + d.y + p.y));
            }
        }
    }
}

__device__ __forceinline__ void epi_bias_gelu(float* __restrict__ dst, int tid,
                                              const float acc[2][8][4],
                                              const float* __restrict__ bias) {
    const int w = tid >> 5, lane = tid & 31;
    const int wm = w & 3, wn = w >> 2;
    const int lr = lane >> 2, lc = lane & 3;
    float* cx = dst + (wm * 32 + lr) * XP + wn * 64 + 2 * lc;
#pragma unroll
    for (int nt = 0; nt < 8; nt++) {
        float2 bv = *(const float2*)(bias + wn * 64 + nt * 8 + 2 * lc);
#pragma unroll
        for (int mt = 0; mt < 2; mt++) {
            *(float2*)(cx + mt * (16 * XP) + nt * 8) =
                make_float2(gelu_exact(acc[mt][nt][0] + bv.x),
                            gelu_exact(acc[mt][nt][1] + bv.y));
            *(float2*)(cx + mt * (16 * XP) + 8 * XP + nt * 8) =
                make_float2(gelu_exact(acc[mt][nt][2] + bv.x),
                            gelu_exact(acc[mt][nt][3] + bv.y));
        }
    }
}

__device__ __forceinline__ void epi_mask_bias(float* __restrict__ dst, int tid,
                                              const float acc[2][8][4],
                                              const float* __restrict__ bias,
                                              const float* __restrict__ sMask) {
    const int w = tid >> 5, lane = tid & 31;
    const int wm = w & 3, wn = w >> 2;
    const int lr = lane >> 2, lc = lane & 3;
    float* cx = dst + (wm * 32 + lr) * XP + wn * 64 + 2 * lc;
#pragma unroll
    for (int mt = 0; mt < 2; mt++) {
        int r0 = wm * 32 + mt * 16 + lr;
        float mk0 = sMask[r0], mk8 = sMask[r0 + 8];
#pragma unroll
        for (int nt = 0; nt < 8; nt++) {
            float2 bv = *(const float2*)(bias + wn * 64 + nt * 8 + 2 * lc);
            *(float2*)(cx + mt * (16 * XP) + nt * 8) =
                make_float2(mk0 * (acc[mt][nt][0] + bv.x), mk0 * (acc[mt][nt][1] + bv.y));
            *(float2*)(cx + mt * (16 * XP) + 8 * XP + nt * 8) =
                make_float2(mk8 * (acc[mt][nt][2] + bv.x), mk8 * (acc[mt][nt][3] + bv.y));
        }
    }
}

// 64-row epilogue: global[row][col] = acc + optional bias (fp32), rows offset p0
__device__ __forceinline__ void epi_to_global64(float* __restrict__ gdst, int p0, int tid,
                                                const float acc[8][4],
                                                const float* __restrict__ bias) {
    const int w = tid >> 5, lane = tid & 31;
    const int wm = w & 3, wn = w >> 2;
    const int lr = lane >> 2, lc = lane & 3;
    const int r0 = wm * 16 + lr;
#pragma unroll
    for (int nt = 0; nt < 8; nt++) {
        int col = wn * 64 + nt * 8 + 2 * lc;
        float2 bv = bias ? *(const float2*)(bias + col) : make_float2(0.f, 0.f);
        *(float2*)(gdst + (size_t)(p0 + r0) * H + col) =
            make_float2(acc[nt][0] + bv.x, acc[nt][1] + bv.y);
        *(float2*)(gdst + (size_t)(p0 + r0 + 8) * H + col) =
            make_float2(acc[nt][2] + bv.x, acc[nt][3] + bv.y);
    }
}

__device__ __forceinline__ void epi_bias_gelu32(float* __restrict__ dst, int tid,
                                                const float acc[2][2][4],
                                                const float* __restrict__ bias) {
    const int w = tid >> 5, lane = tid & 31;
    const int lr = lane >> 2, lc = lane & 3;
    float* cx = dst + lr * XP + w * 16 + 2 * lc;
#pragma unroll
    for (int nt = 0; nt < 2; nt++) {
        float2 bv = *(const float2*)(bias + w * 16 + nt * 8 + 2 * lc);
#pragma unroll
        for (int mt = 0; mt < 2; mt++) {
            *(float2*)(cx + mt * (16 * XP) + nt * 8) =
                make_float2(gelu_exact(acc[mt][nt][0] + bv.x),
                            gelu_exact(acc[mt][nt][1] + bv.y));
            *(float2*)(cx + mt * (16 * XP) + 8 * XP + nt * 8) =
                make_float2(gelu_exact(acc[mt][nt][2] + bv.x),
                            gelu_exact(acc[mt][nt][3] + bv.y));
        }
    }
}

__device__ __forceinline__ void store_acc32(float* __restrict__ dst, int tid,
                                            const float acc[2][2][4]) {
    const int w = tid >> 5, lane = tid & 31;
    const int lr = lane >> 2, lc = lane & 3;
    float* cx = dst + lr * XP + w * 16 + 2 * lc;
#pragma unroll
    for (int mt = 0; mt < 2; mt++)
#pragma unroll
        for (int nt = 0; nt < 2; nt++) {
            *(float2*)(cx + mt * (16 * XP) + nt * 8) =
                make_float2(acc[mt][nt][0], acc[mt][nt][1]);
            *(float2*)(cx + mt * (16 * XP) + 8 * XP + nt * 8) =
                make_float2(acc[mt][nt][2], acc[mt][nt][3]);
        }
}

// ---------------- prep weights: transpose/fold + tf32, natural [n][k] ----------------
__global__ void prep_weights(const float* __restrict__ W1, const float* __restrict__ W2,
                             const float* __restrict__ W3, const float* __restrict__ W11,
                             const float* __restrict__ W12, const float* __restrict__ W13,
                             const float* __restrict__ W_in, const float* __restrict__ W_out) {
    int idx = blockIdx.x * 256 + threadIdx.x;
    if (idx >= 19 * HH) return;
    int m = idx / HH;
    int r = (idx >> 7) & 127;
    int c = idx & 127;
    float v;
    switch (m) {
        case W_E1:  v = W1[(128 + c) * H + r] + W1[(384 + c) * H + r]; break;
        case W_2T:  v = W2[c * H + r]; break;
        case W_3T:  v = W3[c * H + r]; break;
        case W_11E: v = W11[(128 + c) * H + r]; break;
        case W_12T: v = W12[c * H + r]; break;
        case W_13T: v = W13[c * H + r]; break;
        case W_1V:  v = W1[c * H + r]; break;
        case W_1G:  v = W1[(256 + c) * H + r]; break;
        case W_1A:  v = W1[(512 + c) * H + r]; break;
        case W_11V: v = W11[c * H + r]; break;
        case W_11G: v = W11[(256 + c) * H + r]; break;
        default:
            if (m < W_OUTT) {
                int nc = m - W_INT;
                v = W_in[c * 512 + nc * 128 + r];
            } else {
                int kc = m - W_OUTT;
                v = W_out[(kc * 128 + c) * H + r];
            }
            break;
    }
    g_Wt[m * HH + r * H + c] = to_tf32(v);
}

// ---------------- pre1: 64-row tiles, grid (64, 2) ----------------
// smem: sXa [0..8448) | sXb [8448..16896) | sW0 [16896..21504) | sW1 [21504..26112)
__global__ void __launch_bounds__(256)
pre1_mma(const float* __restrict__ hV, const float* __restrict__ hVa,
         const float* __restrict__ b1) {
    extern __shared__ float smf[];
    float* sXa = smf;
    float* sXb = smf + 8448;
    float* sW0 = smf + 16896;
    float* sW1 = smf + 21504;
    const int tid = threadIdx.x;
    const int p0 = blockIdx.x * 64;
    const int z = blockIdx.y;
    const int r = tid >> 2, c0 = (tid & 3) * 32;

    {
        const float* a = hV + (size_t)(p0 + r) * H + c0;
        float* xa = sXa + r * XP + c0;
#pragma unroll
        for (int c = 0; c < 32; c += 4)
            *(float4*)(xa + c) = *(const float4*)(a + c);
        if (z == 1) {
            const float* b = hVa + (size_t)(p0 + r) * H + c0;
            float* xb = sXb + r * XP + c0;
#pragma unroll
            for (int c = 0; c < 32; c += 4)
                *(float4*)(xb + c) = *(const float4*)(b + c);
        }
    }

    float acc[8][4];
    zero_acc8(acc);
    if (z == 0) {
        gemm64_db(sXa, sW0, sW1, g_Wt + W_1V * HH, (const float*)nullptr, false, tid, acc);
        epi_to_global64(g_D1, p0, tid, acc, b1);
    } else {
        gemm64_db(sXa, sW0, sW1, g_Wt + W_1G * HH, g_Wt + W_1A * HH, false, tid, acc);
        gemm64_db(sXb, sW0, sW1, g_Wt + W_1A * HH, (const float*)nullptr, true, tid, acc);
        epi_to_global64(g_P1, p0, tid, acc, (const float*)nullptr);
    }
}

// ---------------- pre2: 64-row tiles, grid (64, 2) ----------------
__global__ void __launch_bounds__(256)
pre2_mma(const float* __restrict__ hVf, const float* __restrict__ b11) {
    extern __shared__ float smf[];
    float* sXa = smf;
    float* sW0 = smf + 8448;
    float* sW1 = smf + 13056;
    const int tid = threadIdx.x;
    const int p0 = blockIdx.x * 64;
    const int z = blockIdx.y;
    const int r = tid >> 2, c0 = (tid & 3) * 32;

    {
        const float* a = hVf + (size_t)(p0 + r) * H + c0;
        float* xa = sXa + r * XP + c0;
#pragma unroll
        for (int c = 0; c < 32; c += 4)
            *(float4*)(xa + c) = *(const float4*)(a + c);
    }

    float acc[8][4];
    zero_acc8(acc);
    if (z == 0) {
        gemm64_db(sXa, sW0, sW1, g_Wt + W_11V * HH, (const float*)nullptr, false, tid, acc);
        epi_to_global64(g_D2, p0, tid, acc, b11);
    } else {
        gemm64_db(sXa, sW0, sW1, g_Wt + W_11G * HH, (const float*)nullptr, false, tid, acc);
        epi_to_global64(g_P2, p0, tid, acc, (const float*)nullptr);
    }
}

// node smem (floats): sX 0..16896 | sW0 16896..21504 | sW1 21504..26112 |
//   sD 26112..27136 | sAcc 27136..28160 | sIdx 28160..28544 (int) |
//   sMask 28544..28672 ; sAcc2 aliases sW1 ; sRed aliases smf+23552 (in sW1, LN only)
#define SMEM_NODE 28672
#define SMEM_EDGE 27520

// ---------------- node message MLP + sum_K + LN1 ----------------
__global__ void __launch_bounds__(256, 2)
node_mma_kernel(const float* __restrict__ hV, const float* __restrict__ hE,
                const float* __restrict__ b2, const float* __restrict__ b3,
                const float* __restrict__ g1, const float* __restrict__ be1,
                const float* __restrict__ maskA, const int* __restrict__ Eidx) {
    extern __shared__ float smf[];
    float* sX    = smf;
    float* sW0   = smf + 16896;
    float* sW1   = smf + 21504;
    float* sAcc2 = sW1;                  // alias: sW1 dead after GEMM3 q3
    float* sRed  = smf + 23552 + 512;    // inside sW1, beyond sAcc2's 2048 floats
    float* sD    = smf + 26112;
    float* sAcc  = smf + 27136;
    int*   sIdx  = (int*)(smf + 28160);
    float* sMask = smf + 28544;

    const int tid = threadIdx.x;
    const int p0 = blockIdx.x * 8;
    const int bb = p0 >> 11;
    const float* P1b = g_P1 + (size_t)bb * NN * H;

    for (int i = tid; i < 8 * H; i += 256) {
        sD[i] = g_D1[(size_t)p0 * H + i];
        sAcc[i] = 0.f;
    }
    for (int i = tid; i < 8 * KNB; i += 256) sIdx[i] = Eidx[(size_t)p0 * KNB + i];

    float acc[2][8][4];

    for (int t = 0; t < 3; t++) {
        const int e0 = p0 * KNB + t * 128;

        __syncthreads();
        stage_rows_async(sX, hE + (size_t)e0 * H, tid);   // raw fp32 tile
        if (tid < 128) sMask[tid] = maskA[e0 + tid];

        // GEMM1 (+prefetch W2) + register epi1
        zero_acc(acc);
        gemm256_db(sX, sW0, sW1, g_Wt + W_E1 * HH, g_Wt + W_2T * HH, t > 0, tid, acc);
        __syncthreads();
        epi1_reg(sX, tid, t * 128, acc, P1b, sIdx + t * 128, sD);

        // GEMM2 (+prefetch W3) + register epi2
        zero_acc(acc);
        gemm256_db(sX, sW0, sW1, g_Wt + W_2T * HH, g_Wt + W_3T * HH, true, tid, acc);
        __syncthreads();
        epi_bias_gelu(sX, tid, acc, b2);

        // GEMM3 (+prefetch next tile's W_E1 into sW0) + register epi3 (mask)
        zero_acc(acc);
        gemm256_db(sX, sW0, sW1, g_Wt + W_3T * HH,
                   (t < 2) ? (g_Wt + W_E1 * HH) : (const float*)nullptr, true, tid, acc);
        __syncthreads();
        epi_mask_bias(sX, tid, acc, b3, sMask);
        for (int i = tid; i < 2048; i += 256) sAcc2[i] = 0.f;
        __syncthreads();

        // segment-sum rows -> per-node partials
        {
            const int col = tid & 127, half = tid >> 7;
            int rr = half * 64;
            int nl = (t * 128 + rr) / KNB;
            int nxt = (nl + 1) * KNB - t * 128;
            float a = 0.f;
            for (; rr < half * 64 + 64; rr++) {
                if (rr == nxt) { sAcc2[half * 1024 + nl * 128 + col] = a; nl++; nxt += KNB; a = 0.f; }
                a += sX[rr * XP + col];
            }
            sAcc2[half * 1024 + nl * 128 + col] = a;
        }
        __syncthreads();
        for (int i = tid; i < 1024; i += 256)
            sAcc[i] += sAcc2[i] + sAcc2[1024 + i];
    }
    __syncthreads();

    // LN1: 2 nodes at a time
    for (int step = 0; step < 4; step++) {
        const int g = tid >> 7;
        const int n = step * 2 + g;
        const int c = tid & 127;
        float u = hV[(size_t)(p0 + n) * H + c] + sAcc[n * 128 + c] * (1.0f / 30.0f);
        float s = u;
#pragma unroll
        for (int off = 16; off > 0; off >>= 1) s += __shfl_xor_sync(0xffffffffu, s, off);
        if ((tid & 31) == 0) sRed[tid >> 5] = s;
        __syncthreads();
        float mean = (sRed[g*4] + sRed[g*4+1] + sRed[g*4+2] + sRed[g*4+3]) * (1.0f / H);
        float d = u - mean;
        float v2 = d * d;
#pragma unroll
        for (int off = 16; off > 0; off >>= 1) v2 += __shfl_xor_sync(0xffffffffu, v2, off);
        if ((tid & 31) == 0) sRed[8 + (tid >> 5)] = v2;
        __syncthreads();
        float var = (sRed[8+g*4] + sRed[8+g*4+1] + sRed[8+g*4+2] + sRed[8+g*4+3]) * (1.0f / H);
        g_hV1[(size_t)(p0 + n) * H + c] = d * rsqrtf(var + 1e-5f) * g1[c] + be1[c];
        __syncthreads();
    }
}

// ---------------- edge update MLP + LN3 ----------------
__global__ void __launch_bounds__(256, 2)
edge_mma_kernel(const float* __restrict__ hE,
                const float* __restrict__ b12, const float* __restrict__ b13,
                const float* __restrict__ g3, const float* __restrict__ be3,
                const int* __restrict__ Eidx, float* __restrict__ outE) {
    extern __shared__ float smf[];
    float* sX   = smf;
    float* sW0  = smf + 16896;
    float* sW1  = smf + 21504;
    float* sD   = smf + 26112;
    int*   sIdx = (int*)(smf + 27136);

    const int tid = threadIdx.x;
    const int w = tid >> 5, lane = tid & 31;
    const int p0 = blockIdx.x * 8;
    const int bb = p0 >> 11;
    const float* P2b = g_P2 + (size_t)bb * NN * H;

    for (int i = tid; i < 8 * H; i += 256) sD[i] = g_D2[(size_t)p0 * H + i];
    for (int i = tid; i < 8 * KNB; i += 256) sIdx[i] = Eidx[(size_t)p0 * KNB + i];

    float b13v[4], g3v[4], be3v[4];
#pragma unroll
    for (int q = 0; q < 4; q++) {
        b13v[q] = b13[lane + 32 * q];
        g3v[q]  = g3[lane + 32 * q];
        be3v[q] = be3[lane + 32 * q];
    }

    float acc[2][8][4];

    for (int t = 0; t < 3; t++) {
        const int e0 = p0 * KNB + t * 128;

        __syncthreads();
        stage_rows_async(sX, hE + (size_t)e0 * H, tid);

        zero_acc(acc);
        gemm256_db(sX, sW0, sW1, g_Wt + W_11E * HH, g_Wt + W_12T * HH, t > 0, tid, acc);
        __syncthreads();
        epi1_reg(sX, tid, t * 128, acc, P2b, sIdx + t * 128, sD);

        zero_acc(acc);
        gemm256_db(sX, sW0, sW1, g_Wt + W_12T * HH, g_Wt + W_13T * HH, true, tid, acc);
        __syncthreads();
        epi_bias_gelu(sX, tid, acc, b12);

        zero_acc(acc);
        gemm256_db(sX, sW0, sW1, g_Wt + W_13T * HH,
                   (t < 2) ? (g_Wt + W_11E * HH) : (const float*)nullptr, true, tid, acc);
        __syncthreads();
        store_acc(sX, tid, acc);
        __syncthreads();

        // LN3 with fused b13 + hE residual: each warp 16 rows
        for (int rr = w * 16; rr < w * 16 + 16; rr++) {
            const float* he = hE + (size_t)(e0 + rr) * H;
            float v[4];
            float ssum = 0.f;
#pragma unroll
            for (int q = 0; q < 4; q++) {
                v[q] = sX[rr * XP + lane + 32 * q] + b13v[q] + he[lane + 32 * q];
                ssum += v[q];
            }
#pragma unroll
            for (int off = 16; off > 0; off >>= 1) ssum += __shfl_xor_sync(0xffffffffu, ssum, off);
            float mean = ssum * (1.0f / H);
            float vs = 0.f;
#pragma unroll
            for (int q = 0; q < 4; q++) { v[q] -= mean; vs += v[q] * v[q]; }
#pragma unroll
            for (int off = 16; off > 0; off >>= 1) vs += __shfl_xor_sync(0xffffffffu, vs, off);
            float rs = rsqrtf(vs * (1.0f / H) + 1e-5f);
#pragma unroll
            for (int q = 0; q < 4; q++)
                outE[(size_t)(e0 + rr) * H + lane + 32 * q] = v[q] * rs * g3v[q] + be3v[q];
        }
        __syncthreads();
    }
}

// ---------------- FFN (tensor): 32 nodes/CTA, grid 128, chained prefetch ----------------
__global__ void __launch_bounds__(256)
ffn_mma(const float* __restrict__ b_in, const float* __restrict__ b_out,
        const float* __restrict__ g2, const float* __restrict__ be2,
        const float* __restrict__ maskV, float* __restrict__ outV) {
    extern __shared__ float smf[];
    float* sXa = smf;
    float* sXb = smf + 4224;
    float* sW0 = smf + 8448;
    float* sW1 = smf + 13056;
    const int tid = threadIdx.x;
    const int w = tid >> 5, lane = tid & 31;
    const int p0 = blockIdx.x * 32;

    {
        const int r = tid >> 3, c0 = (tid & 7) * 16;
        const float* a = g_hV1 + (size_t)(p0 + r) * H + c0;
        float* xa = sXa + r * XP + c0;
#pragma unroll
        for (int c = 0; c < 16; c += 4)
            *(float4*)(xa + c) = *(const float4*)(a + c);
    }

    float acc[2][2][4], acc2[2][2][4];
    zero_acc32(acc2);
#pragma unroll
    for (int nc = 0; nc < 4; nc++) {
        const float* Win  = g_Wt + (W_INT + nc) * HH;
        const float* Wout = g_Wt + (W_OUTT + nc) * HH;
        const float* Wnxt = (nc < 3) ? (g_Wt + (W_INT + nc + 1) * HH) : (const float*)nullptr;
        zero_acc32(acc);
        gemm32_db(sXa, sW0, sW1, Win, Wout, nc > 0, tid, acc);
        __syncthreads();
        epi_bias_gelu32(sXb, tid, acc, b_in + nc * 128);
        gemm32_db(sXb, sW0, sW1, Wout, Wnxt, true, tid, acc2);
    }
    __syncthreads();
    store_acc32(sXb, tid, acc2);
    __syncthreads();

    for (int rr = w * 4; rr < w * 4 + 4; rr++) {
        const size_t row = p0 + rr;
        const float* res = g_hV1 + row * H;
        float u[4];
        float s = 0.f;
#pragma unroll
        for (int q = 0; q < 4; q++) {
            int c = lane + 32 * q;
            u[q] = sXb[rr * XP + c] + res[c] + b_out[c];
            s += u[q];
        }
#pragma unroll
        for (int off = 16; off > 0; off >>= 1) s += __shfl_xor_sync(0xffffffffu, s, off);
        float mean = s * (1.0f / H);
        float vs = 0.f;
#pragma unroll
        for (int q = 0; q < 4; q++) { u[q] -= mean; vs += u[q] * u[q]; }
#pragma unroll
        for (int off = 16; off > 0; off >>= 1) vs += __shfl_xor_sync(0xffffffffu, vs, off);
        float rs = rsqrtf(vs * (1.0f / H) + 1e-5f);
        float mv = maskV[row];
#pragma unroll
        for (int q = 0; q < 4; q++) {
            int c = lane + 32 * q;
            outV[row * H + c] = (u[q] * rs * g2[c] + be2[c]) * mv;
        }
    }
}

// ---------------- launch ----------------
extern "C" void kernel_launch(void* const* d_in, const int* in_sizes, int n_in,
                              void* d_out, int out_size) {
    const float* hV    = (const float*)d_in[0];
    const float* hVa   = (const float*)d_in[1];
    const float* hE    = (const float*)d_in[2];
    const float* W1    = (const float*)d_in[3];
    const float* b1    = (const float*)d_in[4];
    const float* W2    = (const float*)d_in[5];
    const float* b2    = (const float*)d_in[6];
    const float* W3    = (const float*)d_in[7];
    const float* b3    = (const float*)d_in[8];
    const float* W11   = (const float*)d_in[9];
    const float* b11   = (const float*)d_in[10];
    const float* W12   = (const float*)d_in[11];
    const float* b12   = (const float*)d_in[12];
    const float* W13   = (const float*)d_in[13];
    const float* b13   = (const float*)d_in[14];
    const float* W_in  = (const float*)d_in[15];
    const float* b_in  = (const float*)d_in[16];
    const float* W_out = (const float*)d_in[17];
    const float* b_out = (const float*)d_in[18];
    const float* g1    = (const float*)d_in[19];
    const float* be1   = (const float*)d_in[20];
    const float* g2    = (const float*)d_in[21];
    const float* be2   = (const float*)d_in[22];
    const float* g3    = (const float*)d_in[23];
    const float* be3   = (const float*)d_in[24];
    const float* maskV = (const float*)d_in[25];
    const float* maskA = (const float*)d_in[26];
    const int*   Eidx  = (const int*)d_in[27];

    const int BN = in_sizes[0] / H;   // 4096
    float* outV = (float*)d_out;
    float* outE = (float*)d_out + (size_t)BN * H;

    const size_t smemNODE = SMEM_NODE * sizeof(float);  // 112 KB (2 CTAs/SM)
    const size_t smemEDGE = SMEM_EDGE * sizeof(float);  // 107.5 KB
    const size_t smemPRE1 = 26112 * sizeof(float);      // 102 KB
    const size_t smemPRE2 = 17664 * sizeof(float);      // 69 KB
    const size_t smemFFN  = 17664 * sizeof(float);      // 69 KB

    cudaFuncSetAttribute(node_mma_kernel, cudaFuncAttributeMaxDynamicSharedMemorySize, (int)smemNODE);
    cudaFuncSetAttribute(edge_mma_kernel, cudaFuncAttributeMaxDynamicSharedMemorySize, (int)smemEDGE);
    cudaFuncSetAttribute(pre1_mma, cudaFuncAttributeMaxDynamicSharedMemorySize, (int)smemPRE1);
    cudaFuncSetAttribute(pre2_mma, cudaFuncAttributeMaxDynamicSharedMemorySize, (int)smemPRE2);
    cudaFuncSetAttribute(ffn_mma,  cudaFuncAttributeMaxDynamicSharedMemorySize, (int)smemFFN);

    prep_weights<<<(19 * HH + 255) / 256, 256>>>(W1, W2, W3, W11, W12, W13, W_in, W_out);
    pre1_mma<<<dim3(BN / 64, 2), 256, smemPRE1>>>(hV, hVa, b1);
    node_mma_kernel<<<BN / 8, 256, smemNODE>>>(hV, hE, b2, b3, g1, be1, maskA, Eidx);
    ffn_mma<<<BN / 32, 256, smemFFN>>>(b_in, b_out, g2, be2, maskV, outV);
    pre2_mma<<<dim3(BN / 64, 2), 256, smemPRE2>>>(outV, b11);
    edge_mma_kernel<<<BN / 8, 256, smemEDGE>>>(hE, b12, b13, g3, be3, Eidx, outE);
}